// round 1
// baseline (speedup 1.0000x reference)
#include <cuda_runtime.h>

#define NC 4
#define CS 512
#define NS 256
#define HD 512
#define H  256
#define GAMMA_C 12.0f

// Tile config for score kernel
#define TI 32          // i-rows per CTA
#define TJ 16          // j-cols per CTA
#define TK 32          // k per stage
#define TKP 34         // padded row stride (floats): 34*4=136B -> 2-bank shift per row, conflict-free 64b loads

// Scratch: rotated heads (allowed: __device__ globals, no allocation)
__device__ float g_real[NC * CS * H];
__device__ float g_imag[NC * CS * H];

// ---------------- Kernel A: rotate heads by relation phase ----------------
__global__ void rotate_kernel(const float* __restrict__ heads,
                              const float* __restrict__ rel) {
    int i = blockIdx.x;      // 0..2047
    int k = threadIdx.x;     // 0..255
    float re = heads[i * HD + k];
    float im = heads[i * HD + H + k];
    // phase = rel / (EMB_INIT/pi) = rel * (pi/0.05)
    float ph = rel[i * H + k] * 62.8318530717958648f;
    float s, c;
    sincosf(ph, &s, &c);
    g_real[i * H + k] = re * c - im * s;
    g_imag[i * H + k] = re * s + im * c;
}

// ---------------- f32x2 helpers (FFMA2 path, sm_100+) ----------------
__device__ __forceinline__ unsigned long long addx2(unsigned long long a, unsigned long long b) {
    unsigned long long d;
    asm("add.rn.f32x2 %0, %1, %2;" : "=l"(d) : "l"(a), "l"(b));
    return d;
}
__device__ __forceinline__ unsigned long long mulx2(unsigned long long a, unsigned long long b) {
    unsigned long long d;
    asm("mul.rn.f32x2 %0, %1, %2;" : "=l"(d) : "l"(a), "l"(b));
    return d;
}
__device__ __forceinline__ unsigned long long fmax2(unsigned long long a, unsigned long long b, unsigned long long c) {
    unsigned long long d;
    asm("fma.rn.f32x2 %0, %1, %2, %3;" : "=l"(d) : "l"(a), "l"(b), "l"(c));
    return d;
}
__device__ __forceinline__ float sqrt_fast(float x) {
    float y;
    asm("sqrt.approx.f32 %0, %1;" : "=f"(y) : "f"(x));
    return y;
}
__device__ __forceinline__ unsigned long long lds64(const float* p) {
    return *reinterpret_cast<const unsigned long long*>(p);
}

// ---------------- Kernel B: tiled score ----------------
__global__ __launch_bounds__(256) void score_kernel(const float* __restrict__ tails,
                                                    float* __restrict__ out) {
    __shared__ float s_re[TI][TKP];
    __shared__ float s_im[TI][TKP];
    __shared__ float s_tr[TJ][TKP];   // negated tail real
    __shared__ float s_ti[TJ][TKP];   // negated tail imag

    const int tid = threadIdx.x;
    const int c   = blockIdx.z;           // chunk
    const int bi  = blockIdx.x;           // 0..CS/TI-1 = 0..15
    const int bj  = blockIdx.y;           // 0..NS/TJ-1 = 0..15

    const int tjx = tid & 15;             // j within tile (16 lanes span j -> distinct rows, 2-bank shift)
    const int tix = tid >> 4;             // i within tile, RI=2: rows tix and tix+16

    const int gi0 = c * CS + bi * TI;     // global head-row base
    const float* tbase = tails + (size_t)(c * NS + bj * TJ) * HD;

    float accA0 = 0.f, accA1 = 0.f;       // ii=0 lo/hi lanes
    float accB0 = 0.f, accB1 = 0.f;       // ii=1 lo/hi lanes

    for (int k0 = 0; k0 < H; k0 += TK) {
        __syncthreads();
        // ---- stage real/imag: 32 rows x 32 k = 512 float2 each; 2 per thread per array
        #pragma unroll
        for (int t = 0; t < 2; t++) {
            int idx = tid + t * 256;
            int r  = idx >> 4;
            int c2 = (idx & 15) * 2;
            float2 v = *reinterpret_cast<const float2*>(&g_real[(size_t)(gi0 + r) * H + k0 + c2]);
            *reinterpret_cast<float2*>(&s_re[r][c2]) = v;
            float2 w = *reinterpret_cast<const float2*>(&g_imag[(size_t)(gi0 + r) * H + k0 + c2]);
            *reinterpret_cast<float2*>(&s_im[r][c2]) = w;
        }
        // ---- stage tails (negated): 16 rows x 32 k; 1 float2 per thread per array
        {
            int r  = tid >> 4;
            int c2 = (tid & 15) * 2;
            float2 v = *reinterpret_cast<const float2*>(&tbase[(size_t)r * HD + k0 + c2]);
            *reinterpret_cast<float2*>(&s_tr[r][c2]) = make_float2(-v.x, -v.y);
            float2 w = *reinterpret_cast<const float2*>(&tbase[(size_t)r * HD + H + k0 + c2]);
            *reinterpret_cast<float2*>(&s_ti[r][c2]) = make_float2(-w.x, -w.y);
        }
        __syncthreads();

        // ---- compute: k in pairs, packed f32x2
        #pragma unroll
        for (int kk = 0; kk < TK; kk += 2) {
            unsigned long long tr2 = lds64(&s_tr[tjx][kk]);
            unsigned long long ti2 = lds64(&s_ti[tjx][kk]);
            {   // ii = 0
                unsigned long long rr = lds64(&s_re[tix][kk]);
                unsigned long long rm = lds64(&s_im[tix][kk]);
                unsigned long long dr = addx2(rr, tr2);
                unsigned long long di = addx2(rm, ti2);
                unsigned long long s2 = mulx2(dr, dr);
                s2 = fmax2(di, di, s2);
                float lo, hi;
                asm("mov.b64 {%0, %1}, %2;" : "=f"(lo), "=f"(hi) : "l"(s2));
                accA0 += sqrt_fast(lo);
                accA1 += sqrt_fast(hi);
            }
            {   // ii = 1
                unsigned long long rr = lds64(&s_re[tix + 16][kk]);
                unsigned long long rm = lds64(&s_im[tix + 16][kk]);
                unsigned long long dr = addx2(rr, tr2);
                unsigned long long di = addx2(rm, ti2);
                unsigned long long s2 = mulx2(dr, dr);
                s2 = fmax2(di, di, s2);
                float lo, hi;
                asm("mov.b64 {%0, %1}, %2;" : "=f"(lo), "=f"(hi) : "l"(s2));
                accB0 += sqrt_fast(lo);
                accB1 += sqrt_fast(hi);
            }
        }
    }

    const int gj = bj * TJ + tjx;
    const int gi = bi * TI + tix;
    out[((size_t)c * CS + gi)      * NS + gj] = GAMMA_C - (accA0 + accA1);
    out[((size_t)c * CS + gi + 16) * NS + gj] = GAMMA_C - (accB0 + accB1);
}

extern "C" void kernel_launch(void* const* d_in, const int* in_sizes, int n_in,
                              void* d_out, int out_size) {
    const float* heads = (const float*)d_in[0];
    const float* rel   = (const float*)d_in[1];
    const float* tails = (const float*)d_in[2];
    float* out = (float*)d_out;

    rotate_kernel<<<NC * CS, H>>>(heads, rel);
    dim3 grid(CS / TI, NS / TJ, NC);   // (16, 16, 4) = 1024 CTAs
    score_kernel<<<grid, 256>>>(tails, out);
}